// round 2
// baseline (speedup 1.0000x reference)
#include <cuda_runtime.h>
#include <math.h>

#define NN 50000
#define NE 800000
#define DD 128
#define BIGF 1000000000.0f

// ---------------- scratch (static device globals; no allocs) ----------------
__device__ float g_z[NN * DD];      // z = h@W + b   (25.6 MB)
__device__ float g_s[NN];           // z . w_src
__device__ float g_t[NN];           // z . w_dst
__device__ float g_hnew[NN * DD];   // aggregated output (25.6 MB)
__device__ float g_colsum[DD];
__device__ float g_colsq[DD];
// CSR scratch
__device__ int   g_cnt[NN];         // degree counts (then cursor)
__device__ int   g_off[NN + 1];     // CSR offsets
__device__ int   g_cursor[NN];      // fill cursors
__device__ int   g_eidx[NE];        // edge ids grouped by dst
__device__ int   g_srcs[NE];        // src node per CSR slot
__device__ float g_e[NE];           // e -> ex (CSR order)
__device__ float g_coef[NE];        // sigma -> final coef (CSR order)

__device__ __forceinline__ float clamp_inf(float v) {
    return isinf(v) ? BIGF : v;
}

// ---------------- kernel 0: init counters ----------------
__global__ void k_init() {
    int i = blockIdx.x * blockDim.x + threadIdx.x;
    if (i < NN) g_cnt[i] = 0;
    if (i < DD) { g_colsum[i] = 0.0f; g_colsq[i] = 0.0f; }
}

// ---------------- kernel 1: z = h @ W + b, fused attention dots ----------------
__global__ __launch_bounds__(256) void k_gemm(const float* __restrict__ H,
                                              const float* __restrict__ W,
                                              const float* __restrict__ B,
                                              const float* __restrict__ AW) {
    __shared__ float Ws[32 * 128];   // current K-chunk of W   (16 KB)
    __shared__ float As[32 * 64];    // A tile transposed [k][row] (8 KB)

    const int tid = threadIdx.x;
    const int tx = tid & 31;         // lane: cols tx*4 .. tx*4+3
    const int ty = tid >> 5;         // warp: rows ty*8 .. ty*8+7
    const int row0 = blockIdx.x * 64;

    float acc[8][4];
#pragma unroll
    for (int r = 0; r < 8; r++)
#pragma unroll
        for (int c = 0; c < 4; c++) acc[r][c] = 0.0f;

    for (int k0 = 0; k0 < 128; k0 += 32) {
        __syncthreads();
        const float4* wsrc = (const float4*)(W + k0 * 128);
#pragma unroll
        for (int i = tid; i < 1024; i += 256) ((float4*)Ws)[i] = wsrc[i];
#pragma unroll
        for (int l = 0; l < 2; l++) {
            int f = tid * 2 + l;
            int row = f >> 3;
            int kk = (f & 7) * 4;
            float4 v = make_float4(0.f, 0.f, 0.f, 0.f);
            int grow = row0 + row;
            if (grow < NN) v = *(const float4*)&H[grow * 128 + k0 + kk];
            As[(kk + 0) * 64 + row] = v.x;
            As[(kk + 1) * 64 + row] = v.y;
            As[(kk + 2) * 64 + row] = v.z;
            As[(kk + 3) * 64 + row] = v.w;
        }
        __syncthreads();
#pragma unroll
        for (int k = 0; k < 32; k++) {
            float4 b4 = *(float4*)&Ws[k * 128 + tx * 4];
            float4 a0 = *(float4*)&As[k * 64 + ty * 8];
            float4 a1 = *(float4*)&As[k * 64 + ty * 8 + 4];
            float av[8] = {a0.x, a0.y, a0.z, a0.w, a1.x, a1.y, a1.z, a1.w};
#pragma unroll
            for (int r = 0; r < 8; r++) {
                acc[r][0] += av[r] * b4.x;
                acc[r][1] += av[r] * b4.y;
                acc[r][2] += av[r] * b4.z;
                acc[r][3] += av[r] * b4.w;
            }
        }
    }

    float4 bias = *(const float4*)&B[tx * 4];
    float4 ws = *(const float4*)&AW[tx * 4];
    float4 wd = *(const float4*)&AW[DD + tx * 4];
#pragma unroll
    for (int r = 0; r < 8; r++) {
        int grow = row0 + ty * 8 + r;
        if (grow < NN) {
            float4 v;
            v.x = clamp_inf(acc[r][0] + bias.x);
            v.y = clamp_inf(acc[r][1] + bias.y);
            v.z = clamp_inf(acc[r][2] + bias.z);
            v.w = clamp_inf(acc[r][3] + bias.w);
            *(float4*)&g_z[grow * 128 + tx * 4] = v;
            // fused attention dots: lanes of this warp hold the full row
            float sr = v.x * ws.x + v.y * ws.y + v.z * ws.z + v.w * ws.w;
            float tr = v.x * wd.x + v.y * wd.y + v.z * wd.z + v.w * wd.w;
#pragma unroll
            for (int o = 16; o > 0; o >>= 1) {
                sr += __shfl_xor_sync(0xffffffffu, sr, o);
                tr += __shfl_xor_sync(0xffffffffu, tr, o);
            }
            if (tx == 0) { g_s[grow] = sr; g_t[grow] = tr; }
        }
    }
}

// ---------------- kernel 2: degree histogram ----------------
__global__ void k_hist(const int* __restrict__ dst) {
    int i = blockIdx.x * blockDim.x + threadIdx.x;
    if (i < NE) atomicAdd(&g_cnt[dst[i]], 1);
}

// ---------------- kernel 3: exclusive scan (single block) ----------------
__global__ __launch_bounds__(1024) void k_scan() {
    __shared__ int sums[1024];
    const int t = threadIdx.x;
    const int C = (NN + 1023) / 1024;   // 49
    int b = t * C;
    int e = min(b + C, NN);
    int s = 0;
    for (int i = b; i < e; i++) s += g_cnt[i];
    sums[t] = s;
    __syncthreads();
    // Hillis-Steele inclusive scan
    for (int off = 1; off < 1024; off <<= 1) {
        int v = (t >= off) ? sums[t - off] : 0;
        __syncthreads();
        sums[t] += v;
        __syncthreads();
    }
    int running = sums[t] - s;   // exclusive base
    for (int i = b; i < e; i++) {
        g_off[i] = running;
        g_cursor[i] = running;
        running += g_cnt[i];
    }
    if (t == 1023) g_off[NN] = NE;
}

// ---------------- kernel 4: CSR fill ----------------
__global__ void k_fill(const int* __restrict__ dst) {
    int i = blockIdx.x * blockDim.x + threadIdx.x;
    if (i >= NE) return;
    int pos = atomicAdd(&g_cursor[dst[i]], 1);
    g_eidx[pos] = i;
}

// ---------------- kernel 5: fused edge-softmax + aggregate + BN stats ----------------
// one warp per node
__global__ __launch_bounds__(256) void k_node(const int* __restrict__ src,
                                              const float* __restrict__ sigma,
                                              const float* __restrict__ attnb) {
    __shared__ float s_sum[DD];
    __shared__ float s_sq[DD];
    const int tid = threadIdx.x;
    if (tid < DD) { s_sum[tid] = 0.0f; s_sq[tid] = 0.0f; }
    __syncthreads();

    const int lane = tid & 31;
    const int node = blockIdx.x * 8 + (tid >> 5);   // NN = 6250*8 exactly

    const int beg = g_off[node];
    const int end = g_off[node + 1];
    const float tnode = g_t[node];
    const float ab = attnb[0];

    // phase A: logits + max (lane-strided over edges)
    float m = -3.402823466e+38f;
    for (int j = beg + lane; j < end; j += 32) {
        int e = g_eidx[j];
        int si = src[e];
        g_srcs[j] = si;
        float a = clamp_inf(g_s[si] + tnode + ab);
        float ev = (a > 0.0f) ? a : 0.01f * a;
        g_e[j] = ev;
        m = fmaxf(m, ev);
    }
#pragma unroll
    for (int o = 16; o > 0; o >>= 1) m = fmaxf(m, __shfl_xor_sync(0xffffffffu, m, o));

    // phase B: exp + segment sums
    float den = 0.0f, bs = 0.0f;
    for (int j = beg + lane; j < end; j += 32) {
        float ex = __expf(g_e[j] - m);
        float sg = sigma[g_eidx[j]];
        g_e[j] = ex;
        g_coef[j] = sg;
        den += ex;
        bs += sg;
    }
#pragma unroll
    for (int o = 16; o > 0; o >>= 1) {
        den += __shfl_xor_sync(0xffffffffu, den, o);
        bs  += __shfl_xor_sync(0xffffffffu, bs, o);
    }
    float rden = 1.0f / den;
    float rbs = 1.0f / (bs + 1e-6f);

    // phase B2: final per-edge coefficient
    for (int j = beg + lane; j < end; j += 32)
        g_coef[j] = g_e[j] * rden * g_coef[j] * rbs;
    __syncwarp();

    // phase C: gather-accumulate (lane owns 4 columns)
    float4 acc0 = make_float4(0.f, 0.f, 0.f, 0.f);
    float4 acc1 = make_float4(0.f, 0.f, 0.f, 0.f);
    int j = beg;
    for (; j + 1 < end; j += 2) {
        float c0 = g_coef[j],  c1 = g_coef[j + 1];
        int   s0 = g_srcs[j],  s1 = g_srcs[j + 1];
        float4 z0 = *(const float4*)&g_z[s0 * DD + lane * 4];
        float4 z1 = *(const float4*)&g_z[s1 * DD + lane * 4];
        acc0.x += c0 * z0.x; acc0.y += c0 * z0.y; acc0.z += c0 * z0.z; acc0.w += c0 * z0.w;
        acc1.x += c1 * z1.x; acc1.y += c1 * z1.y; acc1.z += c1 * z1.z; acc1.w += c1 * z1.w;
    }
    if (j < end) {
        float c0 = g_coef[j];
        int   s0 = g_srcs[j];
        float4 z0 = *(const float4*)&g_z[s0 * DD + lane * 4];
        acc0.x += c0 * z0.x; acc0.y += c0 * z0.y; acc0.z += c0 * z0.z; acc0.w += c0 * z0.w;
    }
    float4 v;
    v.x = clamp_inf(acc0.x + acc1.x);
    v.y = clamp_inf(acc0.y + acc1.y);
    v.z = clamp_inf(acc0.z + acc1.z);
    v.w = clamp_inf(acc0.w + acc1.w);
    *(float4*)&g_hnew[node * DD + lane * 4] = v;

    // BN stats into smem
    int c = lane * 4;
    atomicAdd(&s_sum[c + 0], v.x); atomicAdd(&s_sq[c + 0], v.x * v.x);
    atomicAdd(&s_sum[c + 1], v.y); atomicAdd(&s_sq[c + 1], v.y * v.y);
    atomicAdd(&s_sum[c + 2], v.z); atomicAdd(&s_sq[c + 2], v.z * v.z);
    atomicAdd(&s_sum[c + 3], v.w); atomicAdd(&s_sq[c + 3], v.w * v.w);

    __syncthreads();
    if (tid < DD) {
        atomicAdd(&g_colsum[tid], s_sum[tid]);
        atomicAdd(&g_colsq[tid], s_sq[tid]);
    }
}

// ---------------- kernel 6: batchnorm + elu ----------------
__global__ void k_bn(float* __restrict__ out, const float* __restrict__ gamma,
                     const float* __restrict__ beta) {
    int idx = blockIdx.x * blockDim.x + threadIdx.x;
    if (idx >= NN * DD) return;
    int c = idx & 127;
    const float inv_n = 1.0f / (float)NN;
    float mu = g_colsum[c] * inv_n;
    float var = g_colsq[c] * inv_n - mu * mu;
    float xb = (g_hnew[idx] - mu) * rsqrtf(var + 1e-5f) * gamma[c] + beta[c];
    out[idx] = (xb > 0.0f) ? xb : expm1f(xb);   // elu
}

// ---------------- launcher ----------------
extern "C" void kernel_launch(void* const* d_in, const int* in_sizes, int n_in,
                              void* d_out, int out_size) {
    const float* h     = (const float*)d_in[0];
    const int*   src   = (const int*)d_in[1];
    const int*   dst   = (const int*)d_in[2];
    const float* sigma = (const float*)d_in[3];
    const float* fcw   = (const float*)d_in[4];
    const float* fcb   = (const float*)d_in[5];
    const float* attnw = (const float*)d_in[6];
    const float* attnb = (const float*)d_in[7];
    const float* gamma = (const float*)d_in[8];
    const float* beta  = (const float*)d_in[9];
    float* out = (float*)d_out;

    k_init<<<(NN + 255) / 256, 256>>>();
    k_hist<<<(NE + 255) / 256, 256>>>(dst);
    k_scan<<<1, 1024>>>();
    k_fill<<<(NE + 255) / 256, 256>>>(dst);
    k_gemm<<<(NN + 63) / 64, 256>>>(h, fcw, fcb, attnw);
    k_node<<<NN / 8, 256>>>(src, sigma, attnb);
    k_bn<<<(NN * DD + 255) / 256, 256>>>(out, gamma, beta);
}

// round 3
// speedup vs baseline: 1.0461x; 1.0461x over previous
#include <cuda_runtime.h>
#include <math.h>
#include <float.h>

#define NN 50000
#define NE 800000
#define DD 128
#define BIGF 1000000000.0f

// ---------------- scratch (static device globals; no allocs) ----------------
__device__ float  g_z[NN * DD];      // z = h@W + b   (25.6 MB)
__device__ float  g_s[NN];           // z . w_src
__device__ float  g_t[NN];           // z . w_dst
__device__ float  g_hnew[NN * DD];   // aggregated output (25.6 MB)
__device__ float  g_colsum[DD];
__device__ float  g_colsq[DD];
__device__ int    g_cnt[NN];         // degree counts
__device__ int    g_off[NN + 1];     // CSR offsets
__device__ int    g_cursor[NN];      // fill cursors
__device__ float4 g_pack[NE];        // per CSR slot: {src(bits), e, sigma, -}

__device__ __forceinline__ float clamp_inf(float v) {
    return isinf(v) ? BIGF : v;
}

// ---------------- kernel 0: init counters ----------------
__global__ void k_init() {
    int i = blockIdx.x * blockDim.x + threadIdx.x;
    if (i < NN) g_cnt[i] = 0;
    if (i < DD) { g_colsum[i] = 0.0f; g_colsq[i] = 0.0f; }
}

// ---------------- kernel 1: z = h @ W + b, fused attention dots ----------------
__global__ __launch_bounds__(256) void k_gemm(const float* __restrict__ H,
                                              const float* __restrict__ W,
                                              const float* __restrict__ B,
                                              const float* __restrict__ AW) {
    __shared__ float Ws[32 * 128];   // current K-chunk of W   (16 KB)
    __shared__ float As[32 * 64];    // A tile transposed [k][row] (8 KB)

    const int tid = threadIdx.x;
    const int tx = tid & 31;         // lane: cols tx*4 .. tx*4+3
    const int ty = tid >> 5;         // warp: rows ty*8 .. ty*8+7
    const int row0 = blockIdx.x * 64;

    float acc[8][4];
#pragma unroll
    for (int r = 0; r < 8; r++)
#pragma unroll
        for (int c = 0; c < 4; c++) acc[r][c] = 0.0f;

    for (int k0 = 0; k0 < 128; k0 += 32) {
        __syncthreads();
        const float4* wsrc = (const float4*)(W + k0 * 128);
#pragma unroll
        for (int i = tid; i < 1024; i += 256) ((float4*)Ws)[i] = wsrc[i];
#pragma unroll
        for (int l = 0; l < 2; l++) {
            int f = tid * 2 + l;
            int row = f >> 3;
            int kk = (f & 7) * 4;
            float4 v = make_float4(0.f, 0.f, 0.f, 0.f);
            int grow = row0 + row;
            if (grow < NN) v = *(const float4*)&H[grow * 128 + k0 + kk];
            As[(kk + 0) * 64 + row] = v.x;
            As[(kk + 1) * 64 + row] = v.y;
            As[(kk + 2) * 64 + row] = v.z;
            As[(kk + 3) * 64 + row] = v.w;
        }
        __syncthreads();
#pragma unroll
        for (int k = 0; k < 32; k++) {
            float4 b4 = *(float4*)&Ws[k * 128 + tx * 4];
            float4 a0 = *(float4*)&As[k * 64 + ty * 8];
            float4 a1 = *(float4*)&As[k * 64 + ty * 8 + 4];
            float av[8] = {a0.x, a0.y, a0.z, a0.w, a1.x, a1.y, a1.z, a1.w};
#pragma unroll
            for (int r = 0; r < 8; r++) {
                acc[r][0] += av[r] * b4.x;
                acc[r][1] += av[r] * b4.y;
                acc[r][2] += av[r] * b4.z;
                acc[r][3] += av[r] * b4.w;
            }
        }
    }

    float4 bias = *(const float4*)&B[tx * 4];
    float4 ws = *(const float4*)&AW[tx * 4];
    float4 wd = *(const float4*)&AW[DD + tx * 4];
#pragma unroll
    for (int r = 0; r < 8; r++) {
        int grow = row0 + ty * 8 + r;
        if (grow < NN) {
            float4 v;
            v.x = clamp_inf(acc[r][0] + bias.x);
            v.y = clamp_inf(acc[r][1] + bias.y);
            v.z = clamp_inf(acc[r][2] + bias.z);
            v.w = clamp_inf(acc[r][3] + bias.w);
            *(float4*)&g_z[grow * 128 + tx * 4] = v;
            float sr = v.x * ws.x + v.y * ws.y + v.z * ws.z + v.w * ws.w;
            float tr = v.x * wd.x + v.y * wd.y + v.z * wd.z + v.w * wd.w;
#pragma unroll
            for (int o = 16; o > 0; o >>= 1) {
                sr += __shfl_xor_sync(0xffffffffu, sr, o);
                tr += __shfl_xor_sync(0xffffffffu, tr, o);
            }
            if (tx == 0) { g_s[grow] = sr; g_t[grow] = tr; }
        }
    }
}

// ---------------- kernel 2: degree histogram ----------------
__global__ void k_hist(const int* __restrict__ dst) {
    int i = blockIdx.x * blockDim.x + threadIdx.x;
    if (i < NE) atomicAdd(&g_cnt[dst[i]], 1);
}

// ---------------- kernel 3: exclusive scan (single block) ----------------
__global__ __launch_bounds__(1024) void k_scan() {
    __shared__ int sums[1024];
    const int t = threadIdx.x;
    const int C = (NN + 1023) / 1024;   // 49
    int b = t * C;
    int e = min(b + C, NN);
    int s = 0;
    for (int i = b; i < e; i++) s += g_cnt[i];
    sums[t] = s;
    __syncthreads();
    for (int off = 1; off < 1024; off <<= 1) {
        int v = (t >= off) ? sums[t - off] : 0;
        __syncthreads();
        sums[t] += v;
        __syncthreads();
    }
    int running = sums[t] - s;   // exclusive base
    for (int i = b; i < e; i++) {
        g_off[i] = running;
        g_cursor[i] = running;
        running += g_cnt[i];
    }
    if (t == 1023) g_off[NN] = NE;
}

// ---------------- kernel 4: CSR fill with packed edge record ----------------
// runs AFTER gemm: computes the edge logit here and packs {src, e, sigma}
__global__ void k_fill(const int* __restrict__ src, const int* __restrict__ dst,
                       const float* __restrict__ sigma,
                       const float* __restrict__ attnb) {
    int i = blockIdx.x * blockDim.x + threadIdx.x;
    if (i >= NE) return;
    int d = dst[i];
    int s = src[i];
    float a = clamp_inf(g_s[s] + g_t[d] + attnb[0]);
    float e = (a > 0.0f) ? a : 0.01f * a;       // leaky relu
    int pos = atomicAdd(&g_cursor[d], 1);
    g_pack[pos] = make_float4(__int_as_float(s), e, sigma[i], 0.0f);
}

// ---------------- kernel 5: fused softmax + aggregate + BN stats ----------------
// one warp per node; all pack accesses contiguous
__global__ __launch_bounds__(256) void k_node() {
    __shared__ float s_sum[DD];
    __shared__ float s_sq[DD];
    const int tid = threadIdx.x;
    if (tid < DD) { s_sum[tid] = 0.0f; s_sq[tid] = 0.0f; }
    __syncthreads();

    const int lane = tid & 31;
    const int node = blockIdx.x * 8 + (tid >> 5);   // NN = 6250*8 exactly

    const int beg = g_off[node];
    const int end = g_off[node + 1];

    // phase A: warp max over e (contiguous, lane-strided)
    float m = -FLT_MAX;
    for (int j = beg + lane; j < end; j += 32)
        m = fmaxf(m, g_pack[j].y);
#pragma unroll
    for (int o = 16; o > 0; o >>= 1) m = fmaxf(m, __shfl_xor_sync(0xffffffffu, m, o));

    // phase B: denom + beta-sum
    float den = 0.0f, bs = 0.0f;
    for (int j = beg + lane; j < end; j += 32) {
        float4 p = g_pack[j];
        den += __expf(p.y - m);
        bs += p.z;
    }
#pragma unroll
    for (int o = 16; o > 0; o >>= 1) {
        den += __shfl_xor_sync(0xffffffffu, den, o);
        bs  += __shfl_xor_sync(0xffffffffu, bs, o);
    }
    float rden = 1.0f / den;
    float rbs = 1.0f / (bs + 1e-6f);

    // phase C: gather-accumulate; pack loads are warp-uniform (L1 broadcast)
    float4 acc0 = make_float4(0.f, 0.f, 0.f, 0.f);
    float4 acc1 = make_float4(0.f, 0.f, 0.f, 0.f);
    int j = beg;
    for (; j + 1 < end; j += 2) {
        float4 p0 = g_pack[j];
        float4 p1 = g_pack[j + 1];
        float c0 = __expf(p0.y - m) * rden * p0.z * rbs;
        float c1 = __expf(p1.y - m) * rden * p1.z * rbs;
        int s0 = __float_as_int(p0.x);
        int s1 = __float_as_int(p1.x);
        float4 z0 = *(const float4*)&g_z[s0 * DD + lane * 4];
        float4 z1 = *(const float4*)&g_z[s1 * DD + lane * 4];
        acc0.x += c0 * z0.x; acc0.y += c0 * z0.y; acc0.z += c0 * z0.z; acc0.w += c0 * z0.w;
        acc1.x += c1 * z1.x; acc1.y += c1 * z1.y; acc1.z += c1 * z1.z; acc1.w += c1 * z1.w;
    }
    if (j < end) {
        float4 p0 = g_pack[j];
        float c0 = __expf(p0.y - m) * rden * p0.z * rbs;
        int s0 = __float_as_int(p0.x);
        float4 z0 = *(const float4*)&g_z[s0 * DD + lane * 4];
        acc0.x += c0 * z0.x; acc0.y += c0 * z0.y; acc0.z += c0 * z0.z; acc0.w += c0 * z0.w;
    }
    float4 v;
    v.x = clamp_inf(acc0.x + acc1.x);
    v.y = clamp_inf(acc0.y + acc1.y);
    v.z = clamp_inf(acc0.z + acc1.z);
    v.w = clamp_inf(acc0.w + acc1.w);
    *(float4*)&g_hnew[node * DD + lane * 4] = v;

    // BN stats into smem, then one global atomic per block
    int c = lane * 4;
    atomicAdd(&s_sum[c + 0], v.x); atomicAdd(&s_sq[c + 0], v.x * v.x);
    atomicAdd(&s_sum[c + 1], v.y); atomicAdd(&s_sq[c + 1], v.y * v.y);
    atomicAdd(&s_sum[c + 2], v.z); atomicAdd(&s_sq[c + 2], v.z * v.z);
    atomicAdd(&s_sum[c + 3], v.w); atomicAdd(&s_sq[c + 3], v.w * v.w);

    __syncthreads();
    if (tid < DD) {
        atomicAdd(&g_colsum[tid], s_sum[tid]);
        atomicAdd(&g_colsq[tid], s_sq[tid]);
    }
}

// ---------------- kernel 6: batchnorm + elu ----------------
__global__ void k_bn(float* __restrict__ out, const float* __restrict__ gamma,
                     const float* __restrict__ beta) {
    int idx = blockIdx.x * blockDim.x + threadIdx.x;
    if (idx >= NN * DD) return;
    int c = idx & 127;
    const float inv_n = 1.0f / (float)NN;
    float mu = g_colsum[c] * inv_n;
    float var = g_colsq[c] * inv_n - mu * mu;
    float xb = (g_hnew[idx] - mu) * rsqrtf(var + 1e-5f) * gamma[c] + beta[c];
    out[idx] = (xb > 0.0f) ? xb : expm1f(xb);   // elu
}

// ---------------- launcher ----------------
extern "C" void kernel_launch(void* const* d_in, const int* in_sizes, int n_in,
                              void* d_out, int out_size) {
    const float* h     = (const float*)d_in[0];
    const int*   src   = (const int*)d_in[1];
    const int*   dst   = (const int*)d_in[2];
    const float* sigma = (const float*)d_in[3];
    const float* fcw   = (const float*)d_in[4];
    const float* fcb   = (const float*)d_in[5];
    const float* attnw = (const float*)d_in[6];
    const float* attnb = (const float*)d_in[7];
    const float* gamma = (const float*)d_in[8];
    const float* beta  = (const float*)d_in[9];
    float* out = (float*)d_out;

    k_init<<<(NN + 255) / 256, 256>>>();
    k_hist<<<(NE + 255) / 256, 256>>>(dst);
    k_scan<<<1, 1024>>>();
    k_gemm<<<(NN + 63) / 64, 256>>>(h, fcw, fcb, attnw);
    k_fill<<<(NE + 255) / 256, 256>>>(src, dst, sigma, attnb);
    k_node<<<NN / 8, 256>>>();
    k_bn<<<(NN * DD + 255) / 256, 256>>>(out, gamma, beta);
}